// round 8
// baseline (speedup 1.0000x reference)
#include <cuda_runtime.h>

#define NATOM 384
#define NB 8
#define KNBR 383
#define NT 4
#define M0 25
#define M1 50
#define M2 100
#define ET 40
#define ER 8
#define EG 5
#define TPB 128
#define HST 60    // h row stride (floats): 5 groups at 12-float (48B) spacing -> bank-disjoint
#define GOF 12    // per-edge-group offset inside h rows (floats)

__device__ int g_perm[NATOM * KNBR];
__device__ int g_boff[NATOM * NT];

__global__ void prep_kernel(const int* __restrict__ types) {
    __shared__ int ts[NATOM];
    int t = threadIdx.x;
    ts[t] = types[t];
    __syncthreads();
    int cnt[NT] = {0, 0, 0, 0};
    for (int j = 0; j < NATOM; j++)
        if (j != t) cnt[ts[j]]++;
    int off[NT];
    off[0] = 0;
    for (int c = 1; c < NT; c++) off[c] = off[c - 1] + cnt[c - 1];
    for (int c = 0; c < NT; c++) g_boff[t * NT + c] = off[c];
    for (int j = 0; j < NATOM; j++)
        if (j != t) {
            int c = ts[j];
            g_perm[t * KNBR + off[c]++] = j;
        }
}

__device__ __forceinline__ float tanh_m(float x) {
    float y;
    asm("tanh.approx.f32 %0, %1;" : "=f"(y) : "f"(x));
    return y;
}

// smem pool offsets (floats)
#define O_W2  0                        // W2r [M1][25][4] = 5000
#define O_W1  5000                     // W1r [M0][25][2] = 1250
#define O_H1  6252                     // h1 [M1][HST] = 3000
#define O_H0  9252                     // h0 [M0][HST] = 1500
#define O_AE  10752                    // aes [3][ET] = 120
#define O_XS  10872                    // xs [ET] = 40
#define O_W0  10912
#define O_B0  10940
#define O_B1  10968
#define O_B2  11020
#define POOL  11120                    // 44480 B

__global__ __launch_bounds__(TPB, 5) void main_kernel(
    const float* __restrict__ coords, const int* __restrict__ types,
    const float* __restrict__ W0, const float* __restrict__ b0,
    const float* __restrict__ W1, const float* __restrict__ b1,
    const float* __restrict__ W2, const float* __restrict__ b2,
    float* __restrict__ out)
{
    __shared__ __align__(16) float P[POOL];
    float* const W2r = P + O_W2;
    float* const W1r = P + O_W1;
    float* const h1s = P + O_H1;
    float* const h0s = P + O_H0;
    float* const aes = P + O_AE;
    float* const xs  = P + O_XS;
    float* const W0s = P + O_W0;
    float* const b0s = P + O_B0;
    float* const b1r = P + O_B1;
    float* const b2r = P + O_B2;

    int t = threadIdx.x;
    int bid = blockIdx.x;
    int n = bid % NATOM;
    int b = bid / NATOM;
    int tc = __ldg(&types[n]);
    float cx = __ldg(&coords[(b * NATOM + n) * 3 + 0]);
    float cy = __ldg(&coords[(b * NATOM + n) * 3 + 1]);
    float cz = __ldg(&coords[(b * NATOM + n) * 3 + 2]);

    // TRANSPOSED lane map: ge fast, gm slow -> few distinct weight addrs per warp
    int gm = t / 5;          // 0..24 for t<125
    int ge = t - gm * 5;     // 0..4
    int e0 = ge * ER;        // dense edge offset (xs/aes)
    int eo = ge * GOF;       // padded offset in h rows
    bool act = (t < 125);

    const float* const h0base = h0s + eo;
    const float* const h1base = h1s + eo;
    const float* const w1base = W1r + gm * 2;
    const float* const w2base = W2r + gm * 4;
    const float* const aeb = aes + e0;

    float Sp[4][3];
#pragma unroll
    for (int q = 0; q < 4; q++) { Sp[q][0] = 0.f; Sp[q][1] = 0.f; Sp[q][2] = 0.f; }

    for (int tn = 0; tn < NT; tn++) {
        __syncthreads();
        int idx = tc * NT + tn;
        for (int k = t; k < M1 * M2; k += TPB) {
            int j = k / M2, m = k - j * M2;
            int g = m % 25, q = m / 25;
            W2r[j * M2 + g * 4 + q] = W2[(size_t)idx * (M1 * M2) + k];
        }
        for (int k = t; k < M0 * M1; k += TPB) {
            int j = k / M1, m = k - j * M1;
            int g = m % 25, p = m / 25;
            W1r[j * M1 + g * 2 + p] = W1[(size_t)idx * (M0 * M1) + k];
        }
        if (t < M0) { W0s[t] = W0[idx * M0 + t]; b0s[t] = b0[idx * M0 + t]; }
        if (t < M1) { int g = t % 25, p = t / 25; b1r[g * 2 + p] = b1[idx * M1 + t]; }
        if (t < M2) { int g = t % 25, q = t / 25; b2r[g * 4 + q] = b2[idx * M2 + t]; }
        __syncthreads();

        int bs = g_boff[n * NT + tn];
        int be = (tn == NT - 1) ? KNBR : g_boff[n * NT + tn + 1];
        int cnt = be - bs;
        const int* pbase = g_perm + n * KNBR + bs;

        for (int t0 = 0; t0 < cnt; t0 += ET) {
            // ---- Stage 0a: geometry (40 threads) ----
            if (t < ET) {
                int gi = t0 + t;
                float x = 0.f, ax = 0.f, ay = 0.f, az = 0.f;
                if (gi < cnt) {
                    int j = __ldg(&pbase[gi]);
                    float rx = cx - __ldg(&coords[(b * NATOM + j) * 3 + 0]);
                    float ry = cy - __ldg(&coords[(b * NATOM + j) * 3 + 1]);
                    float rz = cz - __ldg(&coords[(b * NATOM + j) * 3 + 2]);
                    float d2 = rx * rx + ry * ry + rz * rz;
                    x = rsqrtf(d2);
                    float i2 = x * x;
                    ax = rx * i2; ay = ry * i2; az = rz * i2;
                }
                xs[t] = x;
                aes[0 * ET + t] = ax;
                aes[1 * ET + t] = ay;
                aes[2 * ET + t] = az;
            }
            __syncthreads();

            float h0v[ER];
            // ---- Stage 0b: layer0 ----
            if (act) {
                float w0v = W0s[gm], b0v = b0s[gm];
                float4 xA = *(const float4*)(xs + e0);
                float4 xB = *(const float4*)(xs + e0 + 4);
                h0v[0] = tanh_m(fmaf(xA.x, w0v, b0v));
                h0v[1] = tanh_m(fmaf(xA.y, w0v, b0v));
                h0v[2] = tanh_m(fmaf(xA.z, w0v, b0v));
                h0v[3] = tanh_m(fmaf(xA.w, w0v, b0v));
                h0v[4] = tanh_m(fmaf(xB.x, w0v, b0v));
                h0v[5] = tanh_m(fmaf(xB.y, w0v, b0v));
                h0v[6] = tanh_m(fmaf(xB.z, w0v, b0v));
                h0v[7] = tanh_m(fmaf(xB.w, w0v, b0v));
                *(float4*)(h0s + gm * HST + eo) = make_float4(h0v[0], h0v[1], h0v[2], h0v[3]);
                *(float4*)(h0s + gm * HST + eo + 4) = make_float4(h0v[4], h0v[5], h0v[6], h0v[7]);
            }
            __syncthreads();

            float h1v0[ER], h1v1[ER];
            // ---- Stage 1: 25->50 GEMM ----
            if (act) {
                float acc0[ER], acc1[ER];
                float2 bb = *(const float2*)(b1r + gm * 2);
#pragma unroll
                for (int e = 0; e < ER; e++) { acc0[e] = bb.x; acc1[e] = bb.y; }
#pragma unroll
                for (int j = 0; j < M0; j++) {
                    float2 w = *(const float2*)(w1base + j * M1);
                    float4 A = *(const float4*)(h0base + j * HST);
                    float4 Bv = *(const float4*)(h0base + j * HST + 4);
                    acc0[0] = fmaf(w.x, A.x, acc0[0]); acc1[0] = fmaf(w.y, A.x, acc1[0]);
                    acc0[1] = fmaf(w.x, A.y, acc0[1]); acc1[1] = fmaf(w.y, A.y, acc1[1]);
                    acc0[2] = fmaf(w.x, A.z, acc0[2]); acc1[2] = fmaf(w.y, A.z, acc1[2]);
                    acc0[3] = fmaf(w.x, A.w, acc0[3]); acc1[3] = fmaf(w.y, A.w, acc1[3]);
                    acc0[4] = fmaf(w.x, Bv.x, acc0[4]); acc1[4] = fmaf(w.y, Bv.x, acc1[4]);
                    acc0[5] = fmaf(w.x, Bv.y, acc0[5]); acc1[5] = fmaf(w.y, Bv.y, acc1[5]);
                    acc0[6] = fmaf(w.x, Bv.z, acc0[6]); acc1[6] = fmaf(w.y, Bv.z, acc1[6]);
                    acc0[7] = fmaf(w.x, Bv.w, acc0[7]); acc1[7] = fmaf(w.y, Bv.w, acc1[7]);
                }
#pragma unroll
                for (int e = 0; e < ER; e++) {
                    h1v0[e] = tanh_m(acc0[e]) + h0v[e];
                    h1v1[e] = tanh_m(acc1[e]) + h0v[e];
                }
                *(float4*)(h1s + gm * HST + eo) = make_float4(h1v0[0], h1v0[1], h1v0[2], h1v0[3]);
                *(float4*)(h1s + gm * HST + eo + 4) = make_float4(h1v0[4], h1v0[5], h1v0[6], h1v0[7]);
                *(float4*)(h1s + (gm + 25) * HST + eo) = make_float4(h1v1[0], h1v1[1], h1v1[2], h1v1[3]);
                *(float4*)(h1s + (gm + 25) * HST + eo + 4) = make_float4(h1v1[4], h1v1[5], h1v1[6], h1v1[7]);
            }
            __syncthreads();

            // ---- Stage 2: 50->100 GEMM + combined epilogue ----
            if (act) {
                float acc[4][ER];
                float4 bb = *(const float4*)(b2r + gm * 4);
#pragma unroll
                for (int e = 0; e < ER; e++) {
                    acc[0][e] = bb.x; acc[1][e] = bb.y; acc[2][e] = bb.z; acc[3][e] = bb.w;
                }
                const float* wp = w2base;
                const float* hp = h1base;
                for (int jb = 0; jb < 5; jb++) {
#pragma unroll
                    for (int u = 0; u < 10; u++) {
                        float4 w = *(const float4*)(wp + u * M2);
                        float4 A = *(const float4*)(hp + u * HST);
                        float4 Bv = *(const float4*)(hp + u * HST + 4);
                        acc[0][0] = fmaf(w.x, A.x, acc[0][0]); acc[1][0] = fmaf(w.y, A.x, acc[1][0]);
                        acc[2][0] = fmaf(w.z, A.x, acc[2][0]); acc[3][0] = fmaf(w.w, A.x, acc[3][0]);
                        acc[0][1] = fmaf(w.x, A.y, acc[0][1]); acc[1][1] = fmaf(w.y, A.y, acc[1][1]);
                        acc[2][1] = fmaf(w.z, A.y, acc[2][1]); acc[3][1] = fmaf(w.w, A.y, acc[3][1]);
                        acc[0][2] = fmaf(w.x, A.z, acc[0][2]); acc[1][2] = fmaf(w.y, A.z, acc[1][2]);
                        acc[2][2] = fmaf(w.z, A.z, acc[2][2]); acc[3][2] = fmaf(w.w, A.z, acc[3][2]);
                        acc[0][3] = fmaf(w.x, A.w, acc[0][3]); acc[1][3] = fmaf(w.y, A.w, acc[1][3]);
                        acc[2][3] = fmaf(w.z, A.w, acc[2][3]); acc[3][3] = fmaf(w.w, A.w, acc[3][3]);
                        acc[0][4] = fmaf(w.x, Bv.x, acc[0][4]); acc[1][4] = fmaf(w.y, Bv.x, acc[1][4]);
                        acc[2][4] = fmaf(w.z, Bv.x, acc[2][4]); acc[3][4] = fmaf(w.w, Bv.x, acc[3][4]);
                        acc[0][5] = fmaf(w.x, Bv.y, acc[0][5]); acc[1][5] = fmaf(w.y, Bv.y, acc[1][5]);
                        acc[2][5] = fmaf(w.z, Bv.y, acc[2][5]); acc[3][5] = fmaf(w.w, Bv.y, acc[3][5]);
                        acc[0][6] = fmaf(w.x, Bv.z, acc[0][6]); acc[1][6] = fmaf(w.y, Bv.z, acc[1][6]);
                        acc[2][6] = fmaf(w.z, Bv.z, acc[2][6]); acc[3][6] = fmaf(w.w, Bv.z, acc[3][6]);
                        acc[0][7] = fmaf(w.x, Bv.w, acc[0][7]); acc[1][7] = fmaf(w.y, Bv.w, acc[1][7]);
                        acc[2][7] = fmaf(w.z, Bv.w, acc[2][7]); acc[3][7] = fmaf(w.w, Bv.w, acc[3][7]);
                    }
                    wp += 10 * M2;
                    hp += 10 * HST;
                }
                float4 a0A = *(const float4*)(aeb + 0 * ET);
                float4 a0B = *(const float4*)(aeb + 0 * ET + 4);
                float4 a1A = *(const float4*)(aeb + 1 * ET);
                float4 a1B = *(const float4*)(aeb + 1 * ET + 4);
                float4 a2A = *(const float4*)(aeb + 2 * ET);
                float4 a2B = *(const float4*)(aeb + 2 * ET + 4);
                float a0[8] = {a0A.x, a0A.y, a0A.z, a0A.w, a0B.x, a0B.y, a0B.z, a0B.w};
                float a1[8] = {a1A.x, a1A.y, a1A.z, a1A.w, a1B.x, a1B.y, a1B.z, a1B.w};
                float a2[8] = {a2A.x, a2A.y, a2A.z, a2A.w, a2B.x, a2B.y, a2B.z, a2B.w};
#pragma unroll
                for (int e = 0; e < ER; e++) {
                    float v0 = tanh_m(acc[0][e]) + h1v0[e];
                    float v1 = tanh_m(acc[1][e]) + h1v1[e];
                    float v2 = tanh_m(acc[2][e]) + h1v0[e];
                    float v3 = tanh_m(acc[3][e]) + h1v1[e];
                    Sp[0][0] = fmaf(a0[e], v0, Sp[0][0]); Sp[0][1] = fmaf(a1[e], v0, Sp[0][1]); Sp[0][2] = fmaf(a2[e], v0, Sp[0][2]);
                    Sp[1][0] = fmaf(a0[e], v1, Sp[1][0]); Sp[1][1] = fmaf(a1[e], v1, Sp[1][1]); Sp[1][2] = fmaf(a2[e], v1, Sp[1][2]);
                    Sp[2][0] = fmaf(a0[e], v2, Sp[2][0]); Sp[2][1] = fmaf(a1[e], v2, Sp[2][1]); Sp[2][2] = fmaf(a2[e], v2, Sp[2][2]);
                    Sp[3][0] = fmaf(a0[e], v3, Sp[3][0]); Sp[3][1] = fmaf(a1[e], v3, Sp[3][1]); Sp[3][2] = fmaf(a2[e], v3, Sp[3][2]);
                }
            }
            __syncthreads();
        }
    }

    // ---- Final reduction ----
    float* const Sred = P;
    float* const Sfin = P + EG * M2 * 3;
    if (act) {
#pragma unroll
        for (int q = 0; q < 4; q++) {
            Sred[ge * (M2 * 3) + (gm + 25 * q) * 3 + 0] = Sp[q][0];
            Sred[ge * (M2 * 3) + (gm + 25 * q) * 3 + 1] = Sp[q][1];
            Sred[ge * (M2 * 3) + (gm + 25 * q) * 3 + 2] = Sp[q][2];
        }
    }
    __syncthreads();
    if (t < M2) {
        float s0 = 0.f, s1 = 0.f, s2 = 0.f;
#pragma unroll
        for (int g = 0; g < EG; g++) {
            s0 += Sred[g * (M2 * 3) + t * 3 + 0];
            s1 += Sred[g * (M2 * 3) + t * 3 + 1];
            s2 += Sred[g * (M2 * 3) + t * 3 + 2];
        }
        Sfin[t * 3 + 0] = s0; Sfin[t * 3 + 1] = s1; Sfin[t * 3 + 2] = s2;
    }
    __syncthreads();
    if (t < M2) {
        float s0 = Sfin[t * 3 + 0], s1 = Sfin[t * 3 + 1], s2 = Sfin[t * 3 + 2];
        float4 o;
        o.x = s0 * Sfin[0] + s1 * Sfin[1] + s2 * Sfin[2];
        o.y = s0 * Sfin[3] + s1 * Sfin[4] + s2 * Sfin[5];
        o.z = s0 * Sfin[6] + s1 * Sfin[7] + s2 * Sfin[8];
        o.w = s0 * Sfin[9] + s1 * Sfin[10] + s2 * Sfin[11];
        *(float4*)(out + (size_t)bid * (M2 * 4) + t * 4) = o;
    }
}

extern "C" void kernel_launch(void* const* d_in, const int* in_sizes, int n_in,
                              void* d_out, int out_size)
{
    const float* coords = (const float*)d_in[0];
    const int*   types  = (const int*)d_in[1];
    const float* W0     = (const float*)d_in[2];
    const float* b0     = (const float*)d_in[3];
    const float* W1     = (const float*)d_in[4];
    const float* b1     = (const float*)d_in[5];
    const float* W2     = (const float*)d_in[6];
    const float* b2     = (const float*)d_in[7];
    float* out = (float*)d_out;

    prep_kernel<<<1, NATOM>>>(types);
    main_kernel<<<NB * NATOM, TPB>>>(coords, types, W0, b0, W1, b1, W2, b2, out);
}

// round 9
// speedup vs baseline: 1.0165x; 1.0165x over previous
#include <cuda_runtime.h>

#define NATOM 384
#define NB 8
#define KNBR 383
#define NT 4
#define M0 25
#define M1 50
#define M2 100
#define ET 40
#define ER 8
#define EG 5
#define TPB 128
#define HST 44

typedef unsigned long long u64;

__device__ int g_perm[NATOM * KNBR];
__device__ int g_boff[NATOM * NT];

__global__ void prep_kernel(const int* __restrict__ types) {
    __shared__ int ts[NATOM];
    int t = threadIdx.x;
    ts[t] = types[t];
    __syncthreads();
    int cnt[NT] = {0, 0, 0, 0};
    for (int j = 0; j < NATOM; j++)
        if (j != t) cnt[ts[j]]++;
    int off[NT];
    off[0] = 0;
    for (int c = 1; c < NT; c++) off[c] = off[c - 1] + cnt[c - 1];
    for (int c = 0; c < NT; c++) g_boff[t * NT + c] = off[c];
    for (int j = 0; j < NATOM; j++)
        if (j != t) {
            int c = ts[j];
            g_perm[t * KNBR + off[c]++] = j;
        }
}

__device__ __forceinline__ float tanh_m(float x) {
    float y;
    asm("tanh.approx.f32 %0, %1;" : "=f"(y) : "f"(x));
    return y;
}
__device__ __forceinline__ u64 pack2(float a, float b) {
    u64 r; asm("mov.b64 %0, {%1, %2};" : "=l"(r) : "f"(a), "f"(b)); return r;
}
__device__ __forceinline__ u64 fma2(u64 a, u64 b, u64 c) {
    u64 d; asm("fma.rn.f32x2 %0, %1, %2, %3;" : "=l"(d) : "l"(a), "l"(b), "l"(c)); return d;
}
__device__ __forceinline__ u64 add2(u64 a, u64 b) {
    u64 d; asm("add.rn.f32x2 %0, %1, %2;" : "=l"(d) : "l"(a), "l"(b)); return d;
}
__device__ __forceinline__ void unpack2(u64 v, float& a, float& b) {
    asm("mov.b64 {%0, %1}, %2;" : "=f"(a), "=f"(b) : "l"(v));
}

// smem pool offsets (floats)
#define O_W2  0                      // W2r [M1][25][4] = 5000
#define O_W1  5000                   // W1r [M0][25][2] = 1250
#define O_H1  6252                   // h1 [M1][HST] = 2200
#define O_H0  8452                   // h0 [M0][HST] = 1100
#define O_AE  9552                   // aes [3][ET] = 120
#define O_XS  9672                   // xs [ET] = 40
#define O_W0  9712
#define O_B0  9740
#define O_B1  9768
#define O_B2  9820
#define POOL  9920                   // 39680 B

__global__ __launch_bounds__(TPB, 5) void main_kernel(
    const float* __restrict__ coords, const int* __restrict__ types,
    const float* __restrict__ W0, const float* __restrict__ b0,
    const float* __restrict__ W1, const float* __restrict__ b1,
    const float* __restrict__ W2, const float* __restrict__ b2,
    float* __restrict__ out)
{
    __shared__ __align__(16) float P[POOL];
    float* const W2r = P + O_W2;
    float* const W1r = P + O_W1;
    float* const h1s = P + O_H1;
    float* const h0s = P + O_H0;
    float* const aes = P + O_AE;
    float* const xs  = P + O_XS;
    float* const W0s = P + O_W0;
    float* const b0s = P + O_B0;
    float* const b1r = P + O_B1;
    float* const b2r = P + O_B2;

    int t = threadIdx.x;
    int bid = blockIdx.x;
    int n = bid % NATOM;
    int b = bid / NATOM;
    int tc = __ldg(&types[n]);
    float cx = __ldg(&coords[(b * NATOM + n) * 3 + 0]);
    float cy = __ldg(&coords[(b * NATOM + n) * 3 + 1]);
    float cz = __ldg(&coords[(b * NATOM + n) * 3 + 2]);

    int gm = t % 25;
    int ge = t / 25;
    int e0 = ge * ER;
    bool act = (t < 125);

    const float* const h0base = h0s + e0;
    const float* const h1base = h1s + e0;
    const float* const w1base = W1r + gm * 2;
    const float* const w2base = W2r + gm * 4;
    const float* const aeb = aes + e0;

    u64 Sp2[4][3];
#pragma unroll
    for (int q = 0; q < 4; q++)
#pragma unroll
        for (int c = 0; c < 3; c++) Sp2[q][c] = 0ull;

    for (int tn = 0; tn < NT; tn++) {
        __syncthreads();
        int idx = tc * NT + tn;
        for (int k = t; k < M1 * M2; k += TPB) {
            int j = k / M2, m = k - j * M2;
            int g = m % 25, q = m / 25;
            W2r[j * M2 + g * 4 + q] = W2[(size_t)idx * (M1 * M2) + k];
        }
        for (int k = t; k < M0 * M1; k += TPB) {
            int j = k / M1, m = k - j * M1;
            int g = m % 25, p = m / 25;
            W1r[j * M1 + g * 2 + p] = W1[(size_t)idx * (M0 * M1) + k];
        }
        if (t < M0) { W0s[t] = W0[idx * M0 + t]; b0s[t] = b0[idx * M0 + t]; }
        if (t < M1) { int g = t % 25, p = t / 25; b1r[g * 2 + p] = b1[idx * M1 + t]; }
        if (t < M2) { int g = t % 25, q = t / 25; b2r[g * 4 + q] = b2[idx * M2 + t]; }
        __syncthreads();

        int bs = g_boff[n * NT + tn];
        int be = (tn == NT - 1) ? KNBR : g_boff[n * NT + tn + 1];
        int cnt = be - bs;
        const int* pbase = g_perm + n * KNBR + bs;

        for (int t0 = 0; t0 < cnt; t0 += ET) {
            // ---- Stage 0a: geometry (40 threads) ----
            if (t < ET) {
                int gi = t0 + t;
                float x = 0.f, ax = 0.f, ay = 0.f, az = 0.f;
                if (gi < cnt) {
                    int j = __ldg(&pbase[gi]);
                    float rx = cx - __ldg(&coords[(b * NATOM + j) * 3 + 0]);
                    float ry = cy - __ldg(&coords[(b * NATOM + j) * 3 + 1]);
                    float rz = cz - __ldg(&coords[(b * NATOM + j) * 3 + 2]);
                    float d2 = rx * rx + ry * ry + rz * rz;
                    x = rsqrtf(d2);
                    float i2 = x * x;
                    ax = rx * i2; ay = ry * i2; az = rz * i2;
                }
                xs[t] = x;
                aes[0 * ET + t] = ax;
                aes[1 * ET + t] = ay;
                aes[2 * ET + t] = az;
            }
            __syncthreads();

            u64 h0p[4];
            // ---- Stage 0b: layer0 ----
            if (act) {
                float w0v = W0s[gm], b0v = b0s[gm];
                float4 xA = *(const float4*)(xs + e0);
                float4 xB = *(const float4*)(xs + e0 + 4);
                h0p[0] = pack2(tanh_m(fmaf(xA.x, w0v, b0v)), tanh_m(fmaf(xA.y, w0v, b0v)));
                h0p[1] = pack2(tanh_m(fmaf(xA.z, w0v, b0v)), tanh_m(fmaf(xA.w, w0v, b0v)));
                h0p[2] = pack2(tanh_m(fmaf(xB.x, w0v, b0v)), tanh_m(fmaf(xB.y, w0v, b0v)));
                h0p[3] = pack2(tanh_m(fmaf(xB.z, w0v, b0v)), tanh_m(fmaf(xB.w, w0v, b0v)));
                ulonglong2* d0 = (ulonglong2*)(h0s + gm * HST + e0);
                d0[0] = make_ulonglong2(h0p[0], h0p[1]);
                d0[1] = make_ulonglong2(h0p[2], h0p[3]);
            }
            __syncthreads();

            u64 h1p0[4], h1p1[4];
            // ---- Stage 1: 25->50 GEMM (packed f32x2) ----
            if (act) {
                float2 bb = *(const float2*)(b1r + gm * 2);
                u64 a0[4], a1[4];
                u64 b0p = pack2(bb.x, bb.x), b1p = pack2(bb.y, bb.y);
#pragma unroll
                for (int p = 0; p < 4; p++) { a0[p] = b0p; a1[p] = b1p; }
#pragma unroll
                for (int j = 0; j < M0; j++) {
                    float2 w = *(const float2*)(w1base + j * M1);
                    u64 wx = pack2(w.x, w.x), wy = pack2(w.y, w.y);
                    ulonglong2 A01 = *(const ulonglong2*)(h0base + j * HST);
                    ulonglong2 A23 = *(const ulonglong2*)(h0base + j * HST + 4);
                    a0[0] = fma2(wx, A01.x, a0[0]); a1[0] = fma2(wy, A01.x, a1[0]);
                    a0[1] = fma2(wx, A01.y, a0[1]); a1[1] = fma2(wy, A01.y, a1[1]);
                    a0[2] = fma2(wx, A23.x, a0[2]); a1[2] = fma2(wy, A23.x, a1[2]);
                    a0[3] = fma2(wx, A23.y, a0[3]); a1[3] = fma2(wy, A23.y, a1[3]);
                }
#pragma unroll
                for (int p = 0; p < 4; p++) {
                    float u0, u1, v0, v1;
                    unpack2(a0[p], u0, u1);
                    unpack2(a1[p], v0, v1);
                    h1p0[p] = add2(pack2(tanh_m(u0), tanh_m(u1)), h0p[p]);
                    h1p1[p] = add2(pack2(tanh_m(v0), tanh_m(v1)), h0p[p]);
                }
                ulonglong2* d1 = (ulonglong2*)(h1s + gm * HST + e0);
                d1[0] = make_ulonglong2(h1p0[0], h1p0[1]);
                d1[1] = make_ulonglong2(h1p0[2], h1p0[3]);
                ulonglong2* d2 = (ulonglong2*)(h1s + (gm + 25) * HST + e0);
                d2[0] = make_ulonglong2(h1p1[0], h1p1[1]);
                d2[1] = make_ulonglong2(h1p1[2], h1p1[3]);
            }
            __syncthreads();

            // ---- Stage 2: 50->100 GEMM (packed f32x2) + combined epilogue ----
            if (act) {
                float4 bb = *(const float4*)(b2r + gm * 4);
                u64 acc2[4][4];
                {
                    u64 p0 = pack2(bb.x, bb.x), p1 = pack2(bb.y, bb.y);
                    u64 p2 = pack2(bb.z, bb.z), p3 = pack2(bb.w, bb.w);
#pragma unroll
                    for (int p = 0; p < 4; p++) {
                        acc2[0][p] = p0; acc2[1][p] = p1; acc2[2][p] = p2; acc2[3][p] = p3;
                    }
                }
                const float* wp = w2base;
                const float* hp = h1base;
                for (int jb = 0; jb < 5; jb++) {
#pragma unroll
                    for (int u = 0; u < 10; u++) {
                        float4 w = *(const float4*)(wp + u * M2);
                        ulonglong2 A01 = *(const ulonglong2*)(hp + u * HST);
                        ulonglong2 A23 = *(const ulonglong2*)(hp + u * HST + 4);
                        u64 wx = pack2(w.x, w.x), wy = pack2(w.y, w.y);
                        u64 wz = pack2(w.z, w.z), ww = pack2(w.w, w.w);
                        acc2[0][0] = fma2(wx, A01.x, acc2[0][0]);
                        acc2[0][1] = fma2(wx, A01.y, acc2[0][1]);
                        acc2[0][2] = fma2(wx, A23.x, acc2[0][2]);
                        acc2[0][3] = fma2(wx, A23.y, acc2[0][3]);
                        acc2[1][0] = fma2(wy, A01.x, acc2[1][0]);
                        acc2[1][1] = fma2(wy, A01.y, acc2[1][1]);
                        acc2[1][2] = fma2(wy, A23.x, acc2[1][2]);
                        acc2[1][3] = fma2(wy, A23.y, acc2[1][3]);
                        acc2[2][0] = fma2(wz, A01.x, acc2[2][0]);
                        acc2[2][1] = fma2(wz, A01.y, acc2[2][1]);
                        acc2[2][2] = fma2(wz, A23.x, acc2[2][2]);
                        acc2[2][3] = fma2(wz, A23.y, acc2[2][3]);
                        acc2[3][0] = fma2(ww, A01.x, acc2[3][0]);
                        acc2[3][1] = fma2(ww, A01.y, acc2[3][1]);
                        acc2[3][2] = fma2(ww, A23.x, acc2[3][2]);
                        acc2[3][3] = fma2(ww, A23.y, acc2[3][3]);
                    }
                    wp += 10 * M2;
                    hp += 10 * HST;
                }
                // epilogue: packed aes, v = tanh(acc)+res, S += a*v
                ulonglong2 ae0 = *(const ulonglong2*)(aeb + 0 * ET);
                ulonglong2 ae0b = *(const ulonglong2*)(aeb + 0 * ET + 4);
                ulonglong2 ae1 = *(const ulonglong2*)(aeb + 1 * ET);
                ulonglong2 ae1b = *(const ulonglong2*)(aeb + 1 * ET + 4);
                ulonglong2 ae2 = *(const ulonglong2*)(aeb + 2 * ET);
                ulonglong2 ae2b = *(const ulonglong2*)(aeb + 2 * ET + 4);
                u64 aep[3][4] = {
                    {ae0.x, ae0.y, ae0b.x, ae0b.y},
                    {ae1.x, ae1.y, ae1b.x, ae1b.y},
                    {ae2.x, ae2.y, ae2b.x, ae2b.y}
                };
#pragma unroll
                for (int p = 0; p < 4; p++) {
                    float t00, t01, t10, t11, t20, t21, t30, t31;
                    unpack2(acc2[0][p], t00, t01);
                    unpack2(acc2[1][p], t10, t11);
                    unpack2(acc2[2][p], t20, t21);
                    unpack2(acc2[3][p], t30, t31);
                    u64 v0 = add2(pack2(tanh_m(t00), tanh_m(t01)), h1p0[p]);
                    u64 v1 = add2(pack2(tanh_m(t10), tanh_m(t11)), h1p1[p]);
                    u64 v2 = add2(pack2(tanh_m(t20), tanh_m(t21)), h1p0[p]);
                    u64 v3 = add2(pack2(tanh_m(t30), tanh_m(t31)), h1p1[p]);
#pragma unroll
                    for (int c = 0; c < 3; c++) {
                        Sp2[0][c] = fma2(aep[c][p], v0, Sp2[0][c]);
                        Sp2[1][c] = fma2(aep[c][p], v1, Sp2[1][c]);
                        Sp2[2][c] = fma2(aep[c][p], v2, Sp2[2][c]);
                        Sp2[3][c] = fma2(aep[c][p], v3, Sp2[3][c]);
                    }
                }
            }
            __syncthreads();
        }
    }

    // ---- Final reduction (horizontal add of f32x2 pairs, then block reduce) ----
    float* const Sred = P;
    float* const Sfin = P + EG * M2 * 3;
    if (act) {
#pragma unroll
        for (int q = 0; q < 4; q++) {
#pragma unroll
            for (int c = 0; c < 3; c++) {
                float lo, hi;
                unpack2(Sp2[q][c], lo, hi);
                Sred[ge * (M2 * 3) + (gm + 25 * q) * 3 + c] = lo + hi;
            }
        }
    }
    __syncthreads();
    if (t < M2) {
        float s0 = 0.f, s1 = 0.f, s2 = 0.f;
#pragma unroll
        for (int g = 0; g < EG; g++) {
            s0 += Sred[g * (M2 * 3) + t * 3 + 0];
            s1 += Sred[g * (M2 * 3) + t * 3 + 1];
            s2 += Sred[g * (M2 * 3) + t * 3 + 2];
        }
        Sfin[t * 3 + 0] = s0; Sfin[t * 3 + 1] = s1; Sfin[t * 3 + 2] = s2;
    }
    __syncthreads();
    if (t < M2) {
        float s0 = Sfin[t * 3 + 0], s1 = Sfin[t * 3 + 1], s2 = Sfin[t * 3 + 2];
        float4 o;
        o.x = s0 * Sfin[0] + s1 * Sfin[1] + s2 * Sfin[2];
        o.y = s0 * Sfin[3] + s1 * Sfin[4] + s2 * Sfin[5];
        o.z = s0 * Sfin[6] + s1 * Sfin[7] + s2 * Sfin[8];
        o.w = s0 * Sfin[9] + s1 * Sfin[10] + s2 * Sfin[11];
        *(float4*)(out + (size_t)bid * (M2 * 4) + t * 4) = o;
    }
}

extern "C" void kernel_launch(void* const* d_in, const int* in_sizes, int n_in,
                              void* d_out, int out_size)
{
    const float* coords = (const float*)d_in[0];
    const int*   types  = (const int*)d_in[1];
    const float* W0     = (const float*)d_in[2];
    const float* b0     = (const float*)d_in[3];
    const float* W1     = (const float*)d_in[4];
    const float* b1     = (const float*)d_in[5];
    const float* W2     = (const float*)d_in[6];
    const float* b2     = (const float*)d_in[7];
    float* out = (float*)d_out;

    prep_kernel<<<1, NATOM>>>(types);
    main_kernel<<<NB * NATOM, TPB>>>(coords, types, W0, b0, W1, b1, W2, b2, out);
}

// round 10
// speedup vs baseline: 1.1106x; 1.0926x over previous
#include <cuda_runtime.h>

#define NATOM 384
#define NB 8
#define KNBR 383
#define NT 4
#define M0 25
#define M1 50
#define M2 100
#define ET 40
#define ER 8
#define EG 5
#define TPB 128
#define HST 44

__device__ int g_perm[NATOM * KNBR];
__device__ int g_boff[NATOM * NT];

__global__ void prep_kernel(const int* __restrict__ types) {
    __shared__ int ts[NATOM];
    int t = threadIdx.x;
    ts[t] = types[t];
    __syncthreads();
    int cnt[NT] = {0, 0, 0, 0};
    for (int j = 0; j < NATOM; j++)
        if (j != t) cnt[ts[j]]++;
    int off[NT];
    off[0] = 0;
    for (int c = 1; c < NT; c++) off[c] = off[c - 1] + cnt[c - 1];
    for (int c = 0; c < NT; c++) g_boff[t * NT + c] = off[c];
    for (int j = 0; j < NATOM; j++)
        if (j != t) {
            int c = ts[j];
            g_perm[t * KNBR + off[c]++] = j;
        }
}

__device__ __forceinline__ float tanh_m(float x) {
    float y;
    asm("tanh.approx.f32 %0, %1;" : "=f"(y) : "f"(x));
    return y;
}

// smem pool offsets (floats)
#define O_W2  0                      // W2r [M1][25][4] = 5000
#define O_W1  5000                   // W1r [M0][25][2] = 1250
#define O_H1  6252                   // h1 [M1][HST] = 2200
#define O_H0  8452                   // h0 [M0][HST] = 1100
#define O_AE  9552                   // aes [3][ET] = 120
#define O_XS  9672                   // xs [ET] = 40
#define O_W0  9712
#define O_B0  9740
#define O_B1  9768
#define O_B2  9820
#define POOL  9920                   // 39680 B

__global__ __launch_bounds__(TPB, 5) void main_kernel(
    const float* __restrict__ coords, const int* __restrict__ types,
    const float* __restrict__ W0, const float* __restrict__ b0,
    const float* __restrict__ W1, const float* __restrict__ b1,
    const float* __restrict__ W2, const float* __restrict__ b2,
    float* __restrict__ out)
{
    __shared__ __align__(16) float P[POOL];
    float* const W2r = P + O_W2;
    float* const W1r = P + O_W1;
    float* const h1s = P + O_H1;
    float* const h0s = P + O_H0;
    float* const aes = P + O_AE;
    float* const xs  = P + O_XS;
    float* const W0s = P + O_W0;
    float* const b0s = P + O_B0;
    float* const b1r = P + O_B1;
    float* const b2r = P + O_B2;

    int t = threadIdx.x;
    int bid = blockIdx.x;
    int n = bid % NATOM;
    int b = bid / NATOM;
    int tc = __ldg(&types[n]);
    float cx = __ldg(&coords[(b * NATOM + n) * 3 + 0]);
    float cy = __ldg(&coords[(b * NATOM + n) * 3 + 1]);
    float cz = __ldg(&coords[(b * NATOM + n) * 3 + 2]);

    int gm = t % 25;
    int ge = t / 25;          // 0..4 for t<125
    int e0 = ge * ER;
    bool act = (t < 125);

    const float* const h0base = h0s + e0;
    const float* const h1base = h1s + e0;
    const float* const w1base = W1r + gm * 2;
    const float* const w2base = W2r + gm * 4;
    const float* const aeb = aes + e0;

    float Sp[4][3];
#pragma unroll
    for (int q = 0; q < 4; q++) { Sp[q][0] = 0.f; Sp[q][1] = 0.f; Sp[q][2] = 0.f; }

    for (int tn = 0; tn < NT; tn++) {
        __syncthreads();
        int idx = tc * NT + tn;
        for (int k = t; k < M1 * M2; k += TPB) {
            int j = k / M2, m = k - j * M2;
            int g = m % 25, q = m / 25;
            W2r[j * M2 + g * 4 + q] = W2[(size_t)idx * (M1 * M2) + k];
        }
        for (int k = t; k < M0 * M1; k += TPB) {
            int j = k / M1, m = k - j * M1;
            int g = m % 25, p = m / 25;
            W1r[j * M1 + g * 2 + p] = W1[(size_t)idx * (M0 * M1) + k];
        }
        if (t < M0) { W0s[t] = W0[idx * M0 + t]; b0s[t] = b0[idx * M0 + t]; }
        if (t < M1) { int g = t % 25, p = t / 25; b1r[g * 2 + p] = b1[idx * M1 + t]; }
        if (t < M2) { int g = t % 25, q = t / 25; b2r[g * 4 + q] = b2[idx * M2 + t]; }
        __syncthreads();

        int bs = g_boff[n * NT + tn];
        int be = (tn == NT - 1) ? KNBR : g_boff[n * NT + tn + 1];
        int cnt = be - bs;
        const int* pbase = g_perm + n * KNBR + bs;

        for (int t0 = 0; t0 < cnt; t0 += ET) {
            int rem = cnt - t0;                 // edges in this tile (may be < ET)
            bool glive = act && (e0 < rem);     // whole edge-group live?

            // ---- Stage 0a: geometry (40 threads) ----
            if (t < ET) {
                int gi = t0 + t;
                float x = 0.f, ax = 0.f, ay = 0.f, az = 0.f;
                if (gi < cnt) {
                    int j = __ldg(&pbase[gi]);
                    float rx = cx - __ldg(&coords[(b * NATOM + j) * 3 + 0]);
                    float ry = cy - __ldg(&coords[(b * NATOM + j) * 3 + 1]);
                    float rz = cz - __ldg(&coords[(b * NATOM + j) * 3 + 2]);
                    float d2 = rx * rx + ry * ry + rz * rz;
                    x = rsqrtf(d2);
                    float i2 = x * x;
                    ax = rx * i2; ay = ry * i2; az = rz * i2;
                }
                xs[t] = x;
                aes[0 * ET + t] = ax;
                aes[1 * ET + t] = ay;
                aes[2 * ET + t] = az;
            }
            __syncthreads();

            float h0v[ER];
            // ---- Stage 0b: layer0 (skipped for dead groups) ----
            if (glive) {
                float w0v = W0s[gm], b0v = b0s[gm];
                float4 xA = *(const float4*)(xs + e0);
                float4 xB = *(const float4*)(xs + e0 + 4);
                h0v[0] = tanh_m(fmaf(xA.x, w0v, b0v));
                h0v[1] = tanh_m(fmaf(xA.y, w0v, b0v));
                h0v[2] = tanh_m(fmaf(xA.z, w0v, b0v));
                h0v[3] = tanh_m(fmaf(xA.w, w0v, b0v));
                h0v[4] = tanh_m(fmaf(xB.x, w0v, b0v));
                h0v[5] = tanh_m(fmaf(xB.y, w0v, b0v));
                h0v[6] = tanh_m(fmaf(xB.z, w0v, b0v));
                h0v[7] = tanh_m(fmaf(xB.w, w0v, b0v));
                *(float4*)(h0s + gm * HST + e0) = make_float4(h0v[0], h0v[1], h0v[2], h0v[3]);
                *(float4*)(h0s + gm * HST + e0 + 4) = make_float4(h0v[4], h0v[5], h0v[6], h0v[7]);
            }
            __syncthreads();

            float h1v0[ER], h1v1[ER];
            // ---- Stage 1: 25->50 GEMM + residual-S (skipped for dead groups) ----
            if (glive) {
                float acc0[ER], acc1[ER];
                float2 bb = *(const float2*)(b1r + gm * 2);
#pragma unroll
                for (int e = 0; e < ER; e++) { acc0[e] = bb.x; acc1[e] = bb.y; }
#pragma unroll
                for (int j = 0; j < M0; j++) {
                    float2 w = *(const float2*)(w1base + j * M1);
                    float4 A = *(const float4*)(h0base + j * HST);
                    float4 Bv = *(const float4*)(h0base + j * HST + 4);
                    acc0[0] = fmaf(w.x, A.x, acc0[0]); acc1[0] = fmaf(w.y, A.x, acc1[0]);
                    acc0[1] = fmaf(w.x, A.y, acc0[1]); acc1[1] = fmaf(w.y, A.y, acc1[1]);
                    acc0[2] = fmaf(w.x, A.z, acc0[2]); acc1[2] = fmaf(w.y, A.z, acc1[2]);
                    acc0[3] = fmaf(w.x, A.w, acc0[3]); acc1[3] = fmaf(w.y, A.w, acc1[3]);
                    acc0[4] = fmaf(w.x, Bv.x, acc0[4]); acc1[4] = fmaf(w.y, Bv.x, acc1[4]);
                    acc0[5] = fmaf(w.x, Bv.y, acc0[5]); acc1[5] = fmaf(w.y, Bv.y, acc1[5]);
                    acc0[6] = fmaf(w.x, Bv.z, acc0[6]); acc1[6] = fmaf(w.y, Bv.z, acc1[6]);
                    acc0[7] = fmaf(w.x, Bv.w, acc0[7]); acc1[7] = fmaf(w.y, Bv.w, acc1[7]);
                }
#pragma unroll
                for (int e = 0; e < ER; e++) {
                    h1v0[e] = tanh_m(acc0[e]) + h0v[e];
                    h1v1[e] = tanh_m(acc1[e]) + h0v[e];
                }
                *(float4*)(h1s + gm * HST + e0) = make_float4(h1v0[0], h1v0[1], h1v0[2], h1v0[3]);
                *(float4*)(h1s + gm * HST + e0 + 4) = make_float4(h1v0[4], h1v0[5], h1v0[6], h1v0[7]);
                *(float4*)(h1s + (gm + 25) * HST + e0) = make_float4(h1v1[0], h1v1[1], h1v1[2], h1v1[3]);
                *(float4*)(h1s + (gm + 25) * HST + e0 + 4) = make_float4(h1v1[4], h1v1[5], h1v1[6], h1v1[7]);
            }
            __syncthreads();

            // ---- Stage 2: 50->100 GEMM + combined epilogue (skipped for dead groups) ----
            if (glive) {
                float acc[4][ER];
                float4 bb = *(const float4*)(b2r + gm * 4);
#pragma unroll
                for (int e = 0; e < ER; e++) {
                    acc[0][e] = bb.x; acc[1][e] = bb.y; acc[2][e] = bb.z; acc[3][e] = bb.w;
                }
                const float* wp = w2base;
                const float* hp = h1base;
                for (int jb = 0; jb < 5; jb++) {
#pragma unroll
                    for (int u = 0; u < 10; u++) {
                        float4 w = *(const float4*)(wp + u * M2);
                        float4 A = *(const float4*)(hp + u * HST);
                        float4 Bv = *(const float4*)(hp + u * HST + 4);
                        acc[0][0] = fmaf(w.x, A.x, acc[0][0]); acc[1][0] = fmaf(w.y, A.x, acc[1][0]);
                        acc[2][0] = fmaf(w.z, A.x, acc[2][0]); acc[3][0] = fmaf(w.w, A.x, acc[3][0]);
                        acc[0][1] = fmaf(w.x, A.y, acc[0][1]); acc[1][1] = fmaf(w.y, A.y, acc[1][1]);
                        acc[2][1] = fmaf(w.z, A.y, acc[2][1]); acc[3][1] = fmaf(w.w, A.y, acc[3][1]);
                        acc[0][2] = fmaf(w.x, A.z, acc[0][2]); acc[1][2] = fmaf(w.y, A.z, acc[1][2]);
                        acc[2][2] = fmaf(w.z, A.z, acc[2][2]); acc[3][2] = fmaf(w.w, A.z, acc[3][2]);
                        acc[0][3] = fmaf(w.x, A.w, acc[0][3]); acc[1][3] = fmaf(w.y, A.w, acc[1][3]);
                        acc[2][3] = fmaf(w.z, A.w, acc[2][3]); acc[3][3] = fmaf(w.w, A.w, acc[3][3]);
                        acc[0][4] = fmaf(w.x, Bv.x, acc[0][4]); acc[1][4] = fmaf(w.y, Bv.x, acc[1][4]);
                        acc[2][4] = fmaf(w.z, Bv.x, acc[2][4]); acc[3][4] = fmaf(w.w, Bv.x, acc[3][4]);
                        acc[0][5] = fmaf(w.x, Bv.y, acc[0][5]); acc[1][5] = fmaf(w.y, Bv.y, acc[1][5]);
                        acc[2][5] = fmaf(w.z, Bv.y, acc[2][5]); acc[3][5] = fmaf(w.w, Bv.y, acc[3][5]);
                        acc[0][6] = fmaf(w.x, Bv.z, acc[0][6]); acc[1][6] = fmaf(w.y, Bv.z, acc[1][6]);
                        acc[2][6] = fmaf(w.z, Bv.z, acc[2][6]); acc[3][6] = fmaf(w.w, Bv.z, acc[3][6]);
                        acc[0][7] = fmaf(w.x, Bv.w, acc[0][7]); acc[1][7] = fmaf(w.y, Bv.w, acc[1][7]);
                        acc[2][7] = fmaf(w.z, Bv.w, acc[2][7]); acc[3][7] = fmaf(w.w, Bv.w, acc[3][7]);
                    }
                    wp += 10 * M2;
                    hp += 10 * HST;
                }
                float4 a0A = *(const float4*)(aeb + 0 * ET);
                float4 a0B = *(const float4*)(aeb + 0 * ET + 4);
                float4 a1A = *(const float4*)(aeb + 1 * ET);
                float4 a1B = *(const float4*)(aeb + 1 * ET + 4);
                float4 a2A = *(const float4*)(aeb + 2 * ET);
                float4 a2B = *(const float4*)(aeb + 2 * ET + 4);
                float a0[8] = {a0A.x, a0A.y, a0A.z, a0A.w, a0B.x, a0B.y, a0B.z, a0B.w};
                float a1[8] = {a1A.x, a1A.y, a1A.z, a1A.w, a1B.x, a1B.y, a1B.z, a1B.w};
                float a2[8] = {a2A.x, a2A.y, a2A.z, a2A.w, a2B.x, a2B.y, a2B.z, a2B.w};
#pragma unroll
                for (int e = 0; e < ER; e++) {
                    float v0 = tanh_m(acc[0][e]) + h1v0[e];
                    float v1 = tanh_m(acc[1][e]) + h1v1[e];
                    float v2 = tanh_m(acc[2][e]) + h1v0[e];
                    float v3 = tanh_m(acc[3][e]) + h1v1[e];
                    Sp[0][0] = fmaf(a0[e], v0, Sp[0][0]); Sp[0][1] = fmaf(a1[e], v0, Sp[0][1]); Sp[0][2] = fmaf(a2[e], v0, Sp[0][2]);
                    Sp[1][0] = fmaf(a0[e], v1, Sp[1][0]); Sp[1][1] = fmaf(a1[e], v1, Sp[1][1]); Sp[1][2] = fmaf(a2[e], v1, Sp[1][2]);
                    Sp[2][0] = fmaf(a0[e], v2, Sp[2][0]); Sp[2][1] = fmaf(a1[e], v2, Sp[2][1]); Sp[2][2] = fmaf(a2[e], v2, Sp[2][2]);
                    Sp[3][0] = fmaf(a0[e], v3, Sp[3][0]); Sp[3][1] = fmaf(a1[e], v3, Sp[3][1]); Sp[3][2] = fmaf(a2[e], v3, Sp[3][2]);
                }
            }
            __syncthreads();
        }
    }

    // ---- Final reduction ----
    float* const Sred = P;
    float* const Sfin = P + EG * M2 * 3;
    if (act) {
#pragma unroll
        for (int q = 0; q < 4; q++) {
            Sred[ge * (M2 * 3) + (gm + 25 * q) * 3 + 0] = Sp[q][0];
            Sred[ge * (M2 * 3) + (gm + 25 * q) * 3 + 1] = Sp[q][1];
            Sred[ge * (M2 * 3) + (gm + 25 * q) * 3 + 2] = Sp[q][2];
        }
    }
    __syncthreads();
    if (t < M2) {
        float s0 = 0.f, s1 = 0.f, s2 = 0.f;
#pragma unroll
        for (int g = 0; g < EG; g++) {
            s0 += Sred[g * (M2 * 3) + t * 3 + 0];
            s1 += Sred[g * (M2 * 3) + t * 3 + 1];
            s2 += Sred[g * (M2 * 3) + t * 3 + 2];
        }
        Sfin[t * 3 + 0] = s0; Sfin[t * 3 + 1] = s1; Sfin[t * 3 + 2] = s2;
    }
    __syncthreads();
    if (t < M2) {
        float s0 = Sfin[t * 3 + 0], s1 = Sfin[t * 3 + 1], s2 = Sfin[t * 3 + 2];
        float4 o;
        o.x = s0 * Sfin[0] + s1 * Sfin[1] + s2 * Sfin[2];
        o.y = s0 * Sfin[3] + s1 * Sfin[4] + s2 * Sfin[5];
        o.z = s0 * Sfin[6] + s1 * Sfin[7] + s2 * Sfin[8];
        o.w = s0 * Sfin[9] + s1 * Sfin[10] + s2 * Sfin[11];
        *(float4*)(out + (size_t)bid * (M2 * 4) + t * 4) = o;
    }
}

extern "C" void kernel_launch(void* const* d_in, const int* in_sizes, int n_in,
                              void* d_out, int out_size)
{
    const float* coords = (const float*)d_in[0];
    const int*   types  = (const int*)d_in[1];
    const float* W0     = (const float*)d_in[2];
    const float* b0     = (const float*)d_in[3];
    const float* W1     = (const float*)d_in[4];
    const float* b1     = (const float*)d_in[5];
    const float* W2     = (const float*)d_in[6];
    const float* b2     = (const float*)d_in[7];
    float* out = (float*)d_out;

    prep_kernel<<<1, NATOM>>>(types);
    main_kernel<<<NB * NATOM, TPB>>>(coords, types, W0, b0, W1, b1, W2, b2, out);
}